// round 1
// baseline (speedup 1.0000x reference)
#include <cuda_runtime.h>
#include <cuda_bf16.h>

#define EPS 1e-9f

static constexpr int BMAX = 1024;
static constexpr int DMAX = 512;
static constexpr int UMAX = 512;

// Scratch (device globals — no allocation allowed in kernel_launch)
__device__ float2 g_LN[BMAX * DMAX];   // {log2|x+eps|, neg?1:0}
__device__ float  g_WO[DMAX * UMAX];   // odd(p) ? -w : w

// ---------------- Prepass 1: per (b,d) log2|x+eps| + sign flag ----------------
__global__ void prep_ln_kernel(const float* __restrict__ x, int n) {
    int i = blockIdx.x * blockDim.x + threadIdx.x;
    if (i < n) {
        float xe = x[i] + EPS;
        float l  = log2f(fabsf(xe));      // accurate log2 (prepass is cheap)
        g_LN[i]  = make_float2(l, (xe < 0.f) ? 1.f : 0.f);
    }
}

// ---------------- Prepass 2: per (d,u) signed weight ----------------
__global__ void prep_wo_kernel(const float* __restrict__ w,
                               const float* __restrict__ p, int n) {
    int i = blockIdx.x * blockDim.x + threadIdx.x;
    if (i < n) {
        float pv = p[i];
        float wv = w[i];
        bool odd = (fmodf(pv, 2.f) != 0.f);   // matches jnp.mod(p,2)!=0 truth value
        g_WO[i]  = odd ? -wv : wv;
    }
}

// ---------------- Main kernel: MUFU.EX2-bound inner loop ----------------
// Thread owns 2 u-columns (u0, u0+128). Block: 128 threads -> 256 u-columns,
// TBT=4 b-rows. p/w/wo chunk registers amortized over the 4 b-rows.
static constexpr int DC      = 8;    // d-chunk held in registers
static constexpr int TBT     = 4;    // b-rows per block
static constexpr int THREADS = 128;

__global__ __launch_bounds__(THREADS)
void power_layer_kernel(const float* __restrict__ w,
                        const float* __restrict__ p,
                        const float* __restrict__ bias,
                        float* __restrict__ out,
                        int D, int U) {
    const int u0 = blockIdx.x * (2 * THREADS) + threadIdx.x;
    const int u1 = u0 + THREADS;
    const int b0 = blockIdx.y * TBT;

    float acc[TBT][2];
#pragma unroll
    for (int bb = 0; bb < TBT; bb++) { acc[bb][0] = 0.f; acc[bb][1] = 0.f; }

    for (int d0 = 0; d0 < D; d0 += DC) {
        float pr[DC][2], wr[DC][2], wo[DC][2];
#pragma unroll
        for (int j = 0; j < DC; j++) {
            int r = (d0 + j) * U;
            pr[j][0] = p[r + u0];     pr[j][1] = p[r + u1];
            wr[j][0] = w[r + u0];     wr[j][1] = w[r + u1];
            wo[j][0] = g_WO[r + u0];  wo[j][1] = g_WO[r + u1];
        }

#pragma unroll
        for (int bb = 0; bb < TBT; bb++) {
            const float2* __restrict__ lnp = &g_LN[(size_t)(b0 + bb) * D + d0];
            float2 ln[DC];
#pragma unroll
            for (int j = 0; j < DC; j++) ln[j] = lnp[j];   // warp-uniform -> L1 broadcast

#pragma unroll
            for (int j = 0; j < DC; j++) {
                const bool neg = (ln[j].y != 0.f);
                const float lv = ln[j].x;
#pragma unroll
                for (int t = 0; t < 2; t++) {
                    float e = pr[j][t] * lv;
                    float v;
                    asm("ex2.approx.f32 %0, %1;" : "=f"(v) : "f"(e));
                    float ws = neg ? wo[j][t] : wr[j][t];   // FSEL
                    acc[bb][t] = fmaf(ws, v, acc[bb][t]);
                }
            }
        }
    }

    const float bv0 = bias[u0];
    const float bv1 = bias[u1];
#pragma unroll
    for (int bb = 0; bb < TBT; bb++) {
        out[(size_t)(b0 + bb) * U + u0] = acc[bb][0] + bv0;
        out[(size_t)(b0 + bb) * U + u1] = acc[bb][1] + bv1;
    }
}

// ---------------- Launch ----------------
extern "C" void kernel_launch(void* const* d_in, const int* in_sizes, int n_in,
                              void* d_out, int out_size) {
    const float* x    = (const float*)d_in[0];
    const float* w    = (const float*)d_in[1];
    const float* p    = (const float*)d_in[2];
    const float* bias = (const float*)d_in[3];
    float* out        = (float*)d_out;

    const int U = in_sizes[3];            // 512
    const int D = in_sizes[1] / U;        // 512
    const int B = in_sizes[0] / D;        // 1024

    // Prepasses
    {
        int n = B * D;
        prep_ln_kernel<<<(n + 255) / 256, 256>>>(x, n);
    }
    {
        int n = D * U;
        prep_wo_kernel<<<(n + 255) / 256, 256>>>(w, p, n);
    }

    // Main: grid (U / 256, B / TBT)
    dim3 grid(U / (2 * THREADS), B / TBT);
    power_layer_kernel<<<grid, THREADS>>>(w, p, bias, out, D, U);
}